// round 14
// baseline (speedup 1.0000x reference)
#include <cuda_runtime.h>
#include <cuda_bf16.h>
#include <math.h>

#define DIM     192
#define DSTATE  16
#define DCONV   4
#define DINNER  384
#define DTRANK  12
#define BATCH   8
#define HH      32
#define WW      32
#define LSEQ    1024           // H*W
#define NROW    (BATCH*LSEQ)   // 8192
#define NPROJ   (DTRANK + 2*DSTATE)  // 44

// ---------------- device scratch (allocation-free rule: __device__ globals) ----------------
__device__ float g_a[NROW * 768];     // act1 (pw1 out), later xz (in_proj out)
__device__ float g_b[NROW * DIM];     // ynorm, later seq (pw2 out)
__device__ float g_xc[NROW * DINNER]; // conv1d+silu out
__device__ float g_proj[NROW * NPROJ];
__device__ float g_dt[NROW * DINNER];
__device__ float g_ys[NROW * DINNER]; // scan out, gated in place

// ---------------- K1: depthwise 7x7 conv + bias + LayerNorm -> NHWC (row-major [NROW][DIM]) ----
__global__ __launch_bounds__(192) void k_dwln(
    const float* __restrict__ x, const float* __restrict__ w,
    const float* __restrict__ wb, const float* __restrict__ nw,
    const float* __restrict__ nb, float* __restrict__ out)
{
    int pix = blockIdx.x;                 // 0..8191
    int b   = pix >> 10;
    int hw  = pix & 1023;
    int h   = hw >> 5;
    int wc  = hw & 31;
    int c   = threadIdx.x;                // 0..191

    const float* xc_ = x + (size_t)(b * DIM + c) * LSEQ;
    float acc = wb[c];
    #pragma unroll
    for (int dy = 0; dy < 7; dy++) {
        int hh2 = h + dy - 3;
        if (hh2 < 0 || hh2 > 31) continue;
        #pragma unroll
        for (int dx = 0; dx < 7; dx++) {
            int ww2 = wc + dx - 3;
            if (ww2 < 0 || ww2 > 31) continue;
            acc = fmaf(xc_[hh2 * 32 + ww2], w[(dy * 7 + dx) * DIM + c], acc);
        }
    }

    // block LayerNorm over 192 channels
    __shared__ float s1[6], s2[6], s_mu, s_rs;
    float v1 = acc, v2 = acc * acc;
    #pragma unroll
    for (int o = 16; o; o >>= 1) {
        v1 += __shfl_xor_sync(0xffffffffu, v1, o);
        v2 += __shfl_xor_sync(0xffffffffu, v2, o);
    }
    int wid = c >> 5, lane = c & 31;
    if (lane == 0) { s1[wid] = v1; s2[wid] = v2; }
    __syncthreads();
    if (c == 0) {
        float a = 0.f, q = 0.f;
        #pragma unroll
        for (int i = 0; i < 6; i++) { a += s1[i]; q += s2[i]; }
        float mu  = a * (1.f / DIM);
        float var = q * (1.f / DIM) - mu * mu;
        s_mu = mu;
        s_rs = rsqrtf(var + 1e-6f);
    }
    __syncthreads();
    float o = (acc - s_mu) * s_rs * nw[c] + nb[c];
    out[(size_t)pix * DIM + c] = o;
}

// ---------------- generic tiled fp32 GEMM: C = A[MxK] @ W[KxN] (+bias) (+epilogue) ----------
// EPI: 0 = bias, 1 = bias+GELU(exact), 2 = none, 3 = out_proj (no bias, NHWC->NCHW + residual)
template <int BN, int TN, int EPI>
__global__ __launch_bounds__(256) void gemm_k(
    const float* __restrict__ A, const float* __restrict__ W,
    const float* __restrict__ bias, float* __restrict__ C,
    int M, int N, int K, const float* __restrict__ resid)
{
    constexpr int BM = 128, BK = 8, TM = 8;
    __shared__ float As[BK][BM];
    __shared__ float Ws[BK][BN];

    int tid = threadIdx.x;
    int bm  = blockIdx.y * BM;
    int bn  = blockIdx.x * BN;
    int tx  = tid & 15;   // 16 thread-cols
    int ty  = tid >> 4;   // 16 thread-rows

    float acc[TM][TN];
    #pragma unroll
    for (int i = 0; i < TM; i++)
        #pragma unroll
        for (int j = 0; j < TN; j++) acc[i][j] = 0.f;

    for (int k0 = 0; k0 < K; k0 += BK) {
        #pragma unroll
        for (int i = tid; i < BM * BK; i += 256) {
            int m = i >> 3, k = i & 7;
            As[k][m] = A[(size_t)(bm + m) * K + k0 + k];
        }
        #pragma unroll
        for (int i = tid; i < BK * BN; i += 256) {
            int kk = i / BN, n = i % BN;
            int gn = bn + n;
            Ws[kk][n] = (gn < N) ? W[(size_t)(k0 + kk) * N + gn] : 0.f;
        }
        __syncthreads();
        #pragma unroll
        for (int kk = 0; kk < BK; kk++) {
            float ra[TM], rb[TN];
            #pragma unroll
            for (int i = 0; i < TM; i++) ra[i] = As[kk][ty * TM + i];
            #pragma unroll
            for (int j = 0; j < TN; j++) rb[j] = Ws[kk][tx * TN + j];
            #pragma unroll
            for (int i = 0; i < TM; i++)
                #pragma unroll
                for (int j = 0; j < TN; j++)
                    acc[i][j] = fmaf(ra[i], rb[j], acc[i][j]);
        }
        __syncthreads();
    }

    #pragma unroll
    for (int i = 0; i < TM; i++) {
        int row = bm + ty * TM + i;
        #pragma unroll
        for (int j = 0; j < TN; j++) {
            int col = bn + tx * TN + j;
            if (col >= N) continue;
            float v = acc[i][j];
            if (EPI == 0 || EPI == 1) v += bias[col];
            if (EPI == 1) v = 0.5f * v * (1.f + erff(v * 0.70710678118654752f));
            if (EPI == 3) {
                int bb = row >> 10, hw = row & 1023;
                size_t o = ((size_t)(bb * DIM + col) << 10) + hw;
                C[o] = resid[o] + v;
            } else {
                C[(size_t)row * N + col] = v;
            }
        }
    }
}

// ---------------- K5: causal depthwise conv1d (k=4) + SiLU ----------------
__global__ void k_conv1d(const float* __restrict__ xz, const float* __restrict__ cw,
                         const float* __restrict__ cb, float* __restrict__ xc, int total)
{
    int i = blockIdx.x * blockDim.x + threadIdx.x;
    if (i >= total) return;
    int d = i % DINNER;
    int r = i / DINNER;
    int l = r & 1023;
    int b = r >> 10;
    float acc = cb[d];
    #pragma unroll
    for (int k = 0; k < 4; k++) {
        int ls = l + k - 3;
        if (ls >= 0)
            acc = fmaf(cw[d * 4 + k], xz[(size_t)((b << 10) + ls) * 768 + d], acc);
    }
    float sg = 1.f / (1.f + __expf(-acc));
    xc[i] = acc * sg;
}

// ---------------- K7: dt = softplus(proj[:, :12] @ dt_proj_w + dt_proj_b) ----------------
__global__ __launch_bounds__(DINNER) void k_dt(
    const float* __restrict__ proj, const float* __restrict__ dtw,
    const float* __restrict__ dtb, float* __restrict__ dt)
{
    int row = blockIdx.x;
    int d   = threadIdx.x;
    float acc = dtb[d];
    #pragma unroll
    for (int r = 0; r < DTRANK; r++)
        acc = fmaf(proj[(size_t)row * NPROJ + r], dtw[r * DINNER + d], acc);
    float v = (acc > 20.f) ? acc : log1pf(__expf(acc));
    dt[(size_t)row * DINNER + d] = v;
}

// ---------------- K8: selective scan ----------------
// block = 128 threads = 8 channels x 16 states; one block per (batch, 8-channel group)
__global__ __launch_bounds__(128) void k_scan(
    const float* __restrict__ dt, const float* __restrict__ xc,
    const float* __restrict__ proj, const float* __restrict__ A_log,
    const float* __restrict__ Dp, float* __restrict__ ys)
{
    constexpr int G = 8, CH = 32;          // channels per block, steps per chunk
    __shared__ float s_dt[CH][G];
    __shared__ float s_xc[CH][G];
    __shared__ float s_bc[CH][2 * DSTATE]; // [t][0..15]=B, [t][16..31]=C

    int blk = blockIdx.x;
    int b   = blk / (DINNER / G);
    int d0  = (blk % (DINNER / G)) * G;
    int tid = threadIdx.x;
    int dg  = tid >> 4;       // 0..7
    int n   = tid & 15;       // 0..15
    int d   = d0 + dg;

    float A  = -expf(A_log[d * DSTATE + n]);
    float Dv = Dp[d];
    float h  = 0.f;

    for (int c0 = 0; c0 < LSEQ; c0 += CH) {
        int r0 = (b << 10) + c0;
        // stage chunk
        #pragma unroll
        for (int it = 0; it < 2; it++) {
            int i = tid + it * 128;        // < 256
            int t = i >> 3, g2 = i & 7;
            s_dt[t][g2] = dt[(size_t)(r0 + t) * DINNER + d0 + g2];
            s_xc[t][g2] = xc[(size_t)(r0 + t) * DINNER + d0 + g2];
        }
        #pragma unroll
        for (int it = 0; it < 8; it++) {
            int i = tid + it * 128;        // < 1024
            int t = i >> 5, j = i & 31;
            s_bc[t][j] = proj[(size_t)(r0 + t) * NPROJ + DTRANK + j];
        }
        __syncthreads();

        #pragma unroll 4
        for (int t = 0; t < CH; t++) {
            float dtv = s_dt[t][dg];
            float xv  = s_xc[t][dg];
            float bv  = s_bc[t][n];
            float cv  = s_bc[t][DSTATE + n];
            float dA  = __expf(dtv * A);
            h = fmaf(dA, h, dtv * xv * bv);
            float p = h * cv;
            p += __shfl_xor_sync(0xffffffffu, p, 8);
            p += __shfl_xor_sync(0xffffffffu, p, 4);
            p += __shfl_xor_sync(0xffffffffu, p, 2);
            p += __shfl_xor_sync(0xffffffffu, p, 1);
            if (n == 0)
                ys[(size_t)(r0 + t) * DINNER + d] = p + xv * Dv;
        }
        __syncthreads();
    }
}

// ---------------- K8b: gate: ys *= silu(z) ----------------
__global__ void k_gate(const float* __restrict__ xz, float* __restrict__ ys, int total)
{
    int i = blockIdx.x * blockDim.x + threadIdx.x;
    if (i >= total) return;
    int row = i / DINNER, d = i % DINNER;
    float z  = xz[(size_t)row * 768 + DINNER + d];
    float sg = 1.f / (1.f + __expf(-z));
    ys[i] *= z * sg;
}

// ---------------- launch ----------------
extern "C" void kernel_launch(void* const* d_in, const int* in_sizes, int n_in,
                              void* d_out, int out_size)
{
    const float* x        = (const float*)d_in[0];
    const float* dwconv_w = (const float*)d_in[1];
    const float* dwconv_b = (const float*)d_in[2];
    const float* norm_w   = (const float*)d_in[3];
    const float* norm_b   = (const float*)d_in[4];
    const float* pw1_w    = (const float*)d_in[5];
    const float* pw1_b    = (const float*)d_in[6];
    const float* pw2_w    = (const float*)d_in[7];
    const float* pw2_b    = (const float*)d_in[8];
    const float* in_proj_w= (const float*)d_in[9];
    const float* conv1d_w = (const float*)d_in[10];
    const float* conv1d_b = (const float*)d_in[11];
    const float* x_proj_w = (const float*)d_in[12];
    const float* dt_proj_w= (const float*)d_in[13];
    const float* dt_proj_b= (const float*)d_in[14];
    const float* A_log    = (const float*)d_in[15];
    const float* Dp       = (const float*)d_in[16];
    const float* out_proj_w=(const float*)d_in[17];

    float *ga, *gb, *gxc, *gproj, *gdt, *gys;
    cudaGetSymbolAddress((void**)&ga,   g_a);
    cudaGetSymbolAddress((void**)&gb,   g_b);
    cudaGetSymbolAddress((void**)&gxc,  g_xc);
    cudaGetSymbolAddress((void**)&gproj,g_proj);
    cudaGetSymbolAddress((void**)&gdt,  g_dt);
    cudaGetSymbolAddress((void**)&gys,  g_ys);

    // 1) dwconv + LN -> gb [8192 x 192]
    k_dwln<<<NROW, DIM>>>(x, dwconv_w, dwconv_b, norm_w, norm_b, gb);

    // 2) pw1 + GELU -> ga [8192 x 768]
    gemm_k<128, 8, 1><<<dim3(768 / 128, NROW / 128), 256>>>(
        gb, pw1_w, pw1_b, ga, NROW, 768, DIM, nullptr);

    // 3) pw2 + bias -> gb [8192 x 192]  (= seq)
    gemm_k<64, 4, 0><<<dim3(DIM / 64, NROW / 128), 256>>>(
        ga, pw2_w, pw2_b, gb, NROW, DIM, 768, nullptr);

    // 4) in_proj -> ga [8192 x 768]  (= xz; xm cols 0..383, z cols 384..767)
    gemm_k<128, 8, 2><<<dim3(768 / 128, NROW / 128), 256>>>(
        gb, in_proj_w, nullptr, ga, NROW, 768, DIM, nullptr);

    // 5) causal conv1d + SiLU -> gxc [8192 x 384]
    int tot = NROW * DINNER;
    k_conv1d<<<(tot + 255) / 256, 256>>>(ga, conv1d_w, conv1d_b, gxc, tot);

    // 6) x_proj -> gproj [8192 x 44]
    gemm_k<64, 4, 2><<<dim3(1, NROW / 128), 256>>>(
        gxc, x_proj_w, nullptr, gproj, NROW, NPROJ, DINNER, nullptr);

    // 7) dt = softplus(...) -> gdt [8192 x 384]
    k_dt<<<NROW, DINNER>>>(gproj, dt_proj_w, dt_proj_b, gdt);

    // 8) selective scan (+ xc*D) -> gys [8192 x 384]
    k_scan<<<BATCH * (DINNER / 8), 128>>>(gdt, gxc, gproj, A_log, Dp, gys);

    // 8b) gate: ys *= silu(z)
    k_gate<<<(tot + 255) / 256, 256>>>(ga, gys, tot);

    // 9) out_proj + NCHW transpose + residual -> d_out [8 x 192 x 32 x 32]
    gemm_k<64, 4, 3><<<dim3(DIM / 64, NROW / 128), 256>>>(
        gys, out_proj_w, nullptr, (float*)d_out, NROW, DIM, DINNER, x);
}

// round 15
// speedup vs baseline: 1.4377x; 1.4377x over previous
#include <cuda_runtime.h>
#include <cuda_bf16.h>
#include <math.h>

#define DIM     192
#define DSTATE  16
#define DCONV   4
#define DINNER  384
#define DTRANK  12
#define BATCH   8
#define LSEQ    1024
#define NROW    (BATCH*LSEQ)          // 8192
#define NPROJ   (DTRANK + 2*DSTATE)   // 44

// ---------------- device scratch ----------------
__device__ float g_a[NROW * 768];     // act1 (pw1 out), later xz (in_proj out)
__device__ float g_b[NROW * DIM];     // dwconv out -> LN in-place -> later seq (pw2 out)
__device__ float g_xc[NROW * DINNER]; // conv1d+silu out
__device__ float g_proj[NROW * NPROJ];
__device__ float g_dt[NROW * DINNER];
__device__ float g_ys[NROW * DINNER]; // scan out (gated)

// ---------------- K1a: depthwise 7x7 conv, one block per (b, c) plane ----------------
__global__ __launch_bounds__(256) void k_dw(
    const float* __restrict__ x, const float* __restrict__ w,
    const float* __restrict__ wb, float* __restrict__ out)
{
    __shared__ float sx[38 * 38];
    __shared__ float sw[49];
    int blk = blockIdx.x;            // 0..BATCH*DIM-1
    int b = blk / DIM, c = blk % DIM;
    int tid = threadIdx.x;

    for (int i = tid; i < 38 * 38; i += 256) sx[i] = 0.f;
    if (tid < 49) sw[tid] = w[tid * DIM + c];
    __syncthreads();

    const float* xp = x + (size_t)(b * DIM + c) * 1024;
    #pragma unroll
    for (int it = 0; it < 4; it++) {
        int i = tid + it * 256;
        int h = i >> 5, ww_ = i & 31;
        sx[(h + 3) * 38 + (ww_ + 3)] = xp[i];
    }
    __syncthreads();

    float bias = wb[c];
    #pragma unroll
    for (int it = 0; it < 4; it++) {
        int i = tid + it * 256;
        int h = i >> 5, ww_ = i & 31;
        float acc = bias;
        #pragma unroll
        for (int dy = 0; dy < 7; dy++)
            #pragma unroll
            for (int dx = 0; dx < 7; dx++)
                acc = fmaf(sx[(h + dy) * 38 + ww_ + dx], sw[dy * 7 + dx], acc);
        out[(size_t)((b << 10) + i) * DIM + c] = acc;
    }
}

// ---------------- K1b: LayerNorm in-place over 192 channels, warp per pixel ----------------
__global__ __launch_bounds__(256) void k_ln(
    float* __restrict__ y, const float* __restrict__ nw, const float* __restrict__ nb)
{
    int pix  = blockIdx.x * 8 + (threadIdx.x >> 5);
    int lane = threadIdx.x & 31;
    float* row = y + (size_t)pix * DIM;
    float v[6];
    float s = 0.f, q = 0.f;
    #pragma unroll
    for (int i = 0; i < 6; i++) {
        v[i] = row[i * 32 + lane];
        s += v[i]; q += v[i] * v[i];
    }
    #pragma unroll
    for (int o = 16; o; o >>= 1) {
        s += __shfl_xor_sync(0xffffffffu, s, o);
        q += __shfl_xor_sync(0xffffffffu, q, o);
    }
    float mu = s * (1.f / DIM);
    float rs = rsqrtf(q * (1.f / DIM) - mu * mu + 1e-6f);
    #pragma unroll
    for (int i = 0; i < 6; i++)
        row[i * 32 + lane] = (v[i] - mu) * rs * nw[i * 32 + lane] + nb[i * 32 + lane];
}

// ---------------- vectorized tiled fp32 GEMM ----------------
// EPI: 0 = bias, 1 = bias+GELU(exact), 2 = none, 3 = no bias + NHWC->NCHW + residual
// NG:  true -> scalar, N-guarded loads/stores (for N=44)
template <int BM, int BN, int TM, int TN, int EPI, bool NG>
__global__ __launch_bounds__(256) void gemm2(
    const float* __restrict__ A, const float* __restrict__ W,
    const float* __restrict__ bias, float* __restrict__ C,
    int M, int N, int K, const float* __restrict__ resid)
{
    constexpr int BK  = 8;
    constexpr int TCX = BN / TN;
    constexpr int TCY = BM / TM;
    static_assert(TCX * TCY == 256, "block must be 256 threads");
    constexpr int A4 = BM * 2;   // BM*BK/4 float4 loads for A tile
    constexpr int W4 = BN * 2;   // BK*BN/4 float4 loads for W tile

    __shared__ float As[BK][BM];
    __shared__ float Ws[BK][BN];

    int tid = threadIdx.x;
    int bm  = blockIdx.y * BM;
    int bn  = blockIdx.x * BN;
    int tx  = tid % TCX;
    int ty  = tid / TCX;

    float acc[TM][TN];
    #pragma unroll
    for (int i = 0; i < TM; i++)
        #pragma unroll
        for (int j = 0; j < TN; j++) acc[i][j] = 0.f;

    for (int k0 = 0; k0 < K; k0 += BK) {
        if (!NG) {
            if (A4 == 256 || tid < A4) {
                int m  = tid >> 1;
                int kp = (tid & 1) * 4;
                float4 v = *reinterpret_cast<const float4*>(&A[(size_t)(bm + m) * K + k0 + kp]);
                As[kp + 0][m] = v.x; As[kp + 1][m] = v.y;
                As[kp + 2][m] = v.z; As[kp + 3][m] = v.w;
            }
            if (W4 == 256 || tid < W4) {
                int kk, n4;
                if (BN == 128) { kk = tid >> 5; n4 = tid & 31; }
                else           { kk = tid >> 4; n4 = tid & 15; }
                *reinterpret_cast<float4*>(&Ws[kk][n4 * 4]) =
                    *reinterpret_cast<const float4*>(&W[(size_t)(k0 + kk) * N + bn + n4 * 4]);
            }
        } else {
            #pragma unroll
            for (int i = tid; i < BM * BK; i += 256) {
                int m = i >> 3, k = i & 7;
                As[k][m] = A[(size_t)(bm + m) * K + k0 + k];
            }
            #pragma unroll
            for (int i = tid; i < BK * BN; i += 256) {
                int kk = i / BN, n = i % BN;
                int gn = bn + n;
                Ws[kk][n] = (gn < N) ? W[(size_t)(k0 + kk) * N + gn] : 0.f;
            }
        }
        __syncthreads();

        #pragma unroll
        for (int kk = 0; kk < BK; kk++) {
            float ra[TM], rb[TN];
            #pragma unroll
            for (int i = 0; i < TM; i += 4)
                *reinterpret_cast<float4*>(&ra[i]) =
                    *reinterpret_cast<const float4*>(&As[kk][ty * TM + i]);
            #pragma unroll
            for (int j = 0; j < TN; j += 4)
                *reinterpret_cast<float4*>(&rb[j]) =
                    *reinterpret_cast<const float4*>(&Ws[kk][tx * TN + j]);
            #pragma unroll
            for (int i = 0; i < TM; i++)
                #pragma unroll
                for (int j = 0; j < TN; j++)
                    acc[i][j] = fmaf(ra[i], rb[j], acc[i][j]);
        }
        __syncthreads();
    }

    #pragma unroll
    for (int i = 0; i < TM; i++) {
        int row = bm + ty * TM + i;
        if (EPI == 3) {
            int bb = row >> 10, hw = row & 1023;
            #pragma unroll
            for (int j = 0; j < TN; j++) {
                int col = bn + tx * TN + j;
                size_t o = ((size_t)(bb * DIM + col) << 10) + hw;
                C[o] = resid[o] + acc[i][j];
            }
        } else if (NG) {
            #pragma unroll
            for (int j = 0; j < TN; j++) {
                int col = bn + tx * TN + j;
                if (col < N) C[(size_t)row * N + col] = acc[i][j];
            }
        } else {
            float vout[TN];
            #pragma unroll
            for (int j = 0; j < TN; j++) {
                int col = bn + tx * TN + j;
                float v = acc[i][j];
                if (EPI == 0 || EPI == 1) v += bias[col];
                if (EPI == 1) v = 0.5f * v * (1.f + erff(v * 0.70710678118654752f));
                vout[j] = v;
            }
            #pragma unroll
            for (int j = 0; j < TN; j += 4)
                *reinterpret_cast<float4*>(&C[(size_t)row * N + bn + tx * TN + j]) =
                    make_float4(vout[j], vout[j + 1], vout[j + 2], vout[j + 3]);
        }
    }
}

// ---------------- causal depthwise conv1d (k=4) + SiLU ----------------
__global__ void k_conv1d(const float* __restrict__ xz, const float* __restrict__ cw,
                         const float* __restrict__ cb, float* __restrict__ xc, int total)
{
    int i = blockIdx.x * blockDim.x + threadIdx.x;
    if (i >= total) return;
    int d = i % DINNER;
    int r = i / DINNER;
    int l = r & 1023;
    int b = r >> 10;
    float acc = cb[d];
    #pragma unroll
    for (int k = 0; k < 4; k++) {
        int ls = l + k - 3;
        if (ls >= 0)
            acc = fmaf(cw[d * 4 + k], xz[(size_t)((b << 10) + ls) * 768 + d], acc);
    }
    float sg = 1.f / (1.f + __expf(-acc));
    xc[i] = acc * sg;
}

// ---------------- dt = softplus(proj[:, :12] @ dt_proj_w + dt_proj_b) ----------------
__global__ __launch_bounds__(DINNER) void k_dt(
    const float* __restrict__ proj, const float* __restrict__ dtw,
    const float* __restrict__ dtb, float* __restrict__ dt)
{
    int row = blockIdx.x;
    int d   = threadIdx.x;
    float acc = dtb[d];
    #pragma unroll
    for (int r = 0; r < DTRANK; r++)
        acc = fmaf(proj[(size_t)row * NPROJ + r], dtw[r * DINNER + d], acc);
    float v = (acc > 20.f) ? acc : log1pf(__expf(acc));
    dt[(size_t)row * DINNER + d] = v;
}

// ---------------- selective scan + skip (xc*D) + gate silu(z), fused ----------------
// block = 128 threads = 8 channels x 16 states; one block per (batch, 8-channel group)
__global__ __launch_bounds__(128) void k_scan(
    const float* __restrict__ dt, const float* __restrict__ xc,
    const float* __restrict__ proj, const float* __restrict__ A_log,
    const float* __restrict__ Dp, const float* __restrict__ xz,
    float* __restrict__ ys)
{
    constexpr int G = 8, CH = 32;
    __shared__ float s_dt[CH][G];
    __shared__ float s_xc[CH][G];
    __shared__ float s_z [CH][G];
    __shared__ float s_bc[CH][2 * DSTATE];

    int blk = blockIdx.x;
    int b   = blk / (DINNER / G);
    int d0  = (blk % (DINNER / G)) * G;
    int tid = threadIdx.x;
    int dg  = tid >> 4;
    int n   = tid & 15;
    int d   = d0 + dg;

    float A  = -expf(A_log[d * DSTATE + n]);
    float Dv = Dp[d];
    float h  = 0.f;

    for (int c0 = 0; c0 < LSEQ; c0 += CH) {
        int r0 = (b << 10) + c0;
        #pragma unroll
        for (int it = 0; it < 2; it++) {
            int i = tid + it * 128;
            int t = i >> 3, g2 = i & 7;
            s_dt[t][g2] = dt[(size_t)(r0 + t) * DINNER + d0 + g2];
            s_xc[t][g2] = xc[(size_t)(r0 + t) * DINNER + d0 + g2];
            s_z [t][g2] = xz[(size_t)(r0 + t) * 768 + DINNER + d0 + g2];
        }
        #pragma unroll
        for (int it = 0; it < 8; it++) {
            int i = tid + it * 128;
            int t = i >> 5, j = i & 31;
            s_bc[t][j] = proj[(size_t)(r0 + t) * NPROJ + DTRANK + j];
        }
        __syncthreads();

        #pragma unroll 4
        for (int t = 0; t < CH; t++) {
            float dtv = s_dt[t][dg];
            float xv  = s_xc[t][dg];
            float bv  = s_bc[t][n];
            float cv  = s_bc[t][DSTATE + n];
            float dA  = __expf(dtv * A);
            h = fmaf(dA, h, dtv * xv * bv);
            float p = h * cv;
            p += __shfl_xor_sync(0xffffffffu, p, 8);
            p += __shfl_xor_sync(0xffffffffu, p, 4);
            p += __shfl_xor_sync(0xffffffffu, p, 2);
            p += __shfl_xor_sync(0xffffffffu, p, 1);
            if (n == 0) {
                float z  = s_z[t][dg];
                float sg = 1.f / (1.f + __expf(-z));
                ys[(size_t)(r0 + t) * DINNER + d] = (p + xv * Dv) * (z * sg);
            }
        }
        __syncthreads();
    }
}

// ---------------- launch ----------------
extern "C" void kernel_launch(void* const* d_in, const int* in_sizes, int n_in,
                              void* d_out, int out_size)
{
    const float* x         = (const float*)d_in[0];
    const float* dwconv_w  = (const float*)d_in[1];
    const float* dwconv_b  = (const float*)d_in[2];
    const float* norm_w    = (const float*)d_in[3];
    const float* norm_b    = (const float*)d_in[4];
    const float* pw1_w     = (const float*)d_in[5];
    const float* pw1_b     = (const float*)d_in[6];
    const float* pw2_w     = (const float*)d_in[7];
    const float* pw2_b     = (const float*)d_in[8];
    const float* in_proj_w = (const float*)d_in[9];
    const float* conv1d_w  = (const float*)d_in[10];
    const float* conv1d_b  = (const float*)d_in[11];
    const float* x_proj_w  = (const float*)d_in[12];
    const float* dt_proj_w = (const float*)d_in[13];
    const float* dt_proj_b = (const float*)d_in[14];
    const float* A_log     = (const float*)d_in[15];
    const float* Dp        = (const float*)d_in[16];
    const float* out_proj_w= (const float*)d_in[17];

    float *ga, *gb, *gxc, *gproj, *gdt, *gys;
    cudaGetSymbolAddress((void**)&ga,    g_a);
    cudaGetSymbolAddress((void**)&gb,    g_b);
    cudaGetSymbolAddress((void**)&gxc,   g_xc);
    cudaGetSymbolAddress((void**)&gproj, g_proj);
    cudaGetSymbolAddress((void**)&gdt,   g_dt);
    cudaGetSymbolAddress((void**)&gys,   g_ys);

    // 1) depthwise conv -> gb (NHWC), then LN in-place
    k_dw<<<BATCH * DIM, 256>>>(x, dwconv_w, dwconv_b, gb);
    k_ln<<<NROW / 8, 256>>>(gb, norm_w, norm_b);

    // 2) pw1 + GELU -> ga [8192 x 768]
    gemm2<128, 128, 8, 8, 1, false><<<dim3(6, 64), 256>>>(
        gb, pw1_w, pw1_b, ga, NROW, 768, DIM, nullptr);

    // 3) pw2 + bias -> gb [8192 x 192]
    gemm2<128, 64, 8, 4, 0, false><<<dim3(3, 64), 256>>>(
        ga, pw2_w, pw2_b, gb, NROW, DIM, 768, nullptr);

    // 4) in_proj -> ga [8192 x 768] (xm = cols 0..383, z = cols 384..767)
    gemm2<128, 128, 8, 8, 2, false><<<dim3(6, 64), 256>>>(
        gb, in_proj_w, nullptr, ga, NROW, 768, DIM, nullptr);

    // 5) causal conv1d + SiLU -> gxc
    int tot = NROW * DINNER;
    k_conv1d<<<(tot + 255) / 256, 256>>>(ga, conv1d_w, conv1d_b, gxc, tot);

    // 6) x_proj -> gproj [8192 x 44]
    gemm2<64, 64, 4, 4, 2, true><<<dim3(1, 128), 256>>>(
        gxc, x_proj_w, nullptr, gproj, NROW, NPROJ, DINNER, nullptr);

    // 7) dt
    k_dt<<<NROW, DINNER>>>(gproj, dt_proj_w, dt_proj_b, gdt);

    // 8) selective scan + skip + gate -> gys
    k_scan<<<BATCH * (DINNER / 8), 128>>>(gdt, gxc, gproj, A_log, Dp, ga, gys);

    // 9) out_proj + NCHW transpose + residual -> d_out
    gemm2<128, 64, 8, 4, 3, false><<<dim3(3, 64), 256>>>(
        gys, out_proj_w, nullptr, (float*)d_out, NROW, DIM, DINNER, x);
}

// round 17
// speedup vs baseline: 1.4806x; 1.0298x over previous
#include <cuda_runtime.h>
#include <cuda_bf16.h>
#include <math.h>

#define DIM     192
#define DSTATE  16
#define DCONV   4
#define DINNER  384
#define DTRANK  12
#define BATCH   8
#define LSEQ    1024
#define NROW    (BATCH*LSEQ)          // 8192
#define NPROJ   (DTRANK + 2*DSTATE)   // 44

// ---------------- device scratch ----------------
__device__ float g_a[NROW * 768];     // act1 (pw1 out), later xz (in_proj out)
__device__ float g_b[NROW * DIM];     // dwconv out -> LN in-place -> seq (pw2 out)
__device__ float g_xc[NROW * DINNER]; // conv1d+silu out
__device__ float g_proj[NROW * NPROJ];
__device__ float g_dt[NROW * DINNER];
__device__ float g_ys[NROW * DINNER]; // scan out (gated)

// ---------------- K1a: depthwise 7x7 conv, one block per (b, c) plane ----------------
__global__ __launch_bounds__(256) void k_dw(
    const float* __restrict__ x, const float* __restrict__ w,
    const float* __restrict__ wb, float* __restrict__ out)
{
    __shared__ float sx[38 * 38];
    __shared__ float sw[49];
    int blk = blockIdx.x;
    int b = blk / DIM, c = blk % DIM;
    int tid = threadIdx.x;

    for (int i = tid; i < 38 * 38; i += 256) sx[i] = 0.f;
    if (tid < 49) sw[tid] = w[tid * DIM + c];
    __syncthreads();

    const float* xp = x + (size_t)(b * DIM + c) * 1024;
    #pragma unroll
    for (int it = 0; it < 4; it++) {
        int i = tid + it * 256;
        int h = i >> 5, ww_ = i & 31;
        sx[(h + 3) * 38 + (ww_ + 3)] = xp[i];
    }
    __syncthreads();

    float bias = wb[c];
    #pragma unroll
    for (int it = 0; it < 4; it++) {
        int i = tid + it * 256;
        int h = i >> 5, ww_ = i & 31;
        float acc = bias;
        #pragma unroll
        for (int dy = 0; dy < 7; dy++)
            #pragma unroll
            for (int dx = 0; dx < 7; dx++)
                acc = fmaf(sx[(h + dy) * 38 + ww_ + dx], sw[dy * 7 + dx], acc);
        out[(size_t)((b << 10) + i) * DIM + c] = acc;
    }
}

// ---------------- K1b: LayerNorm in-place, warp per pixel ----------------
__global__ __launch_bounds__(256) void k_ln(
    float* __restrict__ y, const float* __restrict__ nw, const float* __restrict__ nb)
{
    int pix  = blockIdx.x * 8 + (threadIdx.x >> 5);
    int lane = threadIdx.x & 31;
    float* row = y + (size_t)pix * DIM;
    float v[6];
    float s = 0.f, q = 0.f;
    #pragma unroll
    for (int i = 0; i < 6; i++) {
        v[i] = row[i * 32 + lane];
        s += v[i]; q += v[i] * v[i];
    }
    #pragma unroll
    for (int o = 16; o; o >>= 1) {
        s += __shfl_xor_sync(0xffffffffu, s, o);
        q += __shfl_xor_sync(0xffffffffu, q, o);
    }
    float mu = s * (1.f / DIM);
    float rs = rsqrtf(q * (1.f / DIM) - mu * mu + 1e-6f);
    #pragma unroll
    for (int i = 0; i < 6; i++)
        row[i * 32 + lane] = (v[i] - mu) * rs * nw[i * 32 + lane] + nb[i * 32 + lane];
}

// ---------------- double-buffered vectorized fp32 GEMM ----------------
// EPI: 0 = +bias, 1 = +bias+GELU(exact), 2 = none, 3 = NHWC->NCHW transpose + residual
template <int BM, int BN, int TM, int TN, int EPI>
__global__ __launch_bounds__(256) void gemm3(
    const float* __restrict__ A, const float* __restrict__ W,
    const float* __restrict__ bias, float* __restrict__ C,
    int M, int N, int K, const float* __restrict__ resid)
{
    constexpr int BK  = 8;
    constexpr int TCX = BN / TN;
    constexpr int TCY = BM / TM;
    static_assert(TCX * TCY == 256, "block must be 256 threads");
    constexpr int A4 = BM * 2;   // float4 loads for A tile (BM*BK/4)
    constexpr int W4 = BN * 2;   // float4 loads for W tile (BK*BN/4)
    constexpr bool SPLIT = (A4 + W4 <= 256); // disjoint loader threads
    constexpr int WN4 = BN / 4;

    __shared__ float As[2][BK][BM];
    __shared__ float Ws[2][BK][BN];

    int tid = threadIdx.x;
    int bm  = blockIdx.y * BM;
    int bn  = blockIdx.x * BN;
    int tx  = tid % TCX;
    int ty  = tid / TCX;

    // loader roles
    bool doA, doW;
    int am = 0, akp = 0, wkk = 0, wn4 = 0;
    if (SPLIT) {
        doA = tid < A4;
        doW = !doA && tid < A4 + W4;
        if (doA) { am = tid >> 1; akp = (tid & 1) * 4; }
        else     { int t2 = tid - A4; wkk = t2 / WN4; wn4 = t2 % WN4; }
    } else {
        doA = (A4 == 256) || tid < A4;
        doW = (W4 == 256) || tid < W4;
        am = tid >> 1; akp = (tid & 1) * 4;
        wkk = tid / WN4; wn4 = tid % WN4;
    }

    const float* Ap = A + (size_t)(bm + am) * K + akp;
    const float* Wp = W + (size_t)wkk * N + bn + wn4 * 4;

    float acc[TM][TN];
    #pragma unroll
    for (int i = 0; i < TM; i++)
        #pragma unroll
        for (int j = 0; j < TN; j++) acc[i][j] = 0.f;

    int nT = K / BK;
    float4 pa = make_float4(0, 0, 0, 0), pw = make_float4(0, 0, 0, 0);
    if (doA) pa = *reinterpret_cast<const float4*>(Ap);
    if (doW) pw = *reinterpret_cast<const float4*>(Wp);
    {
        if (doA) {
            As[0][akp + 0][am] = pa.x; As[0][akp + 1][am] = pa.y;
            As[0][akp + 2][am] = pa.z; As[0][akp + 3][am] = pa.w;
        }
        if (doW) *reinterpret_cast<float4*>(&Ws[0][wkk][wn4 * 4]) = pw;
    }
    __syncthreads();

    for (int t = 0; t < nT; t++) {
        int cur = t & 1;
        if (t + 1 < nT) {
            if (doA) pa = *reinterpret_cast<const float4*>(Ap + (size_t)(t + 1) * BK);
            if (doW) pw = *reinterpret_cast<const float4*>(Wp + (size_t)(t + 1) * BK * N);
        }
        #pragma unroll
        for (int kk = 0; kk < BK; kk++) {
            float ra[TM], rb[TN];
            #pragma unroll
            for (int i = 0; i < TM; i += 4)
                *reinterpret_cast<float4*>(&ra[i]) =
                    *reinterpret_cast<const float4*>(&As[cur][kk][ty * TM + i]);
            #pragma unroll
            for (int j = 0; j < TN; j += 4)
                *reinterpret_cast<float4*>(&rb[j]) =
                    *reinterpret_cast<const float4*>(&Ws[cur][kk][tx * TN + j]);
            #pragma unroll
            for (int i = 0; i < TM; i++)
                #pragma unroll
                for (int j = 0; j < TN; j++)
                    acc[i][j] = fmaf(ra[i], rb[j], acc[i][j]);
        }
        if (t + 1 < nT) {
            int nxt = cur ^ 1;
            if (doA) {
                As[nxt][akp + 0][am] = pa.x; As[nxt][akp + 1][am] = pa.y;
                As[nxt][akp + 2][am] = pa.z; As[nxt][akp + 3][am] = pa.w;
            }
            if (doW) *reinterpret_cast<float4*>(&Ws[nxt][wkk][wn4 * 4]) = pw;
            __syncthreads();
        }
    }

    if constexpr (EPI == 3) {
        // transpose tile via smem: st[channel][pixel], then coalesced NCHW + residual
        static_assert(TM == 4 && TN == 4 && BM == 64 && BN == 64, "EPI3 config");
        __shared__ float st[64][65];
        #pragma unroll
        for (int i = 0; i < TM; i++)
            #pragma unroll
            for (int j = 0; j < TN; j++)
                st[tx * TN + j][ty * TM + i] = acc[i][j];
        __syncthreads();
        int bb  = bm >> 10;          // BM=64 stripe stays within one batch
        int hw0 = bm & 1023;
        int c2  = tid >> 2;          // 0..63 channel within tile
        int q   = tid & 3;           // 16-float chunk along pixels
        size_t obase = ((size_t)(bb * DIM + bn + c2) << 10) + hw0 + q * 16;
        #pragma unroll
        for (int k4 = 0; k4 < 4; k4++) {
            float4 r = *reinterpret_cast<const float4*>(&resid[obase + k4 * 4]);
            float4 v;
            v.x = r.x + st[c2][q * 16 + k4 * 4 + 0];
            v.y = r.y + st[c2][q * 16 + k4 * 4 + 1];
            v.z = r.z + st[c2][q * 16 + k4 * 4 + 2];
            v.w = r.w + st[c2][q * 16 + k4 * 4 + 3];
            *reinterpret_cast<float4*>(&C[obase + k4 * 4]) = v;
        }
    } else {
        #pragma unroll
        for (int i = 0; i < TM; i++) {
            int row = bm + ty * TM + i;
            float vout[TN];
            #pragma unroll
            for (int j = 0; j < TN; j++) {
                int col = bn + tx * TN + j;
                float v = acc[i][j];
                if constexpr (EPI == 0 || EPI == 1) v += bias[col];
                if constexpr (EPI == 1) v = 0.5f * v * (1.f + erff(v * 0.70710678118654752f));
                vout[j] = v;
            }
            #pragma unroll
            for (int j = 0; j < TN; j += 4)
                *reinterpret_cast<float4*>(&C[(size_t)row * N + bn + tx * TN + j]) =
                    make_float4(vout[j], vout[j + 1], vout[j + 2], vout[j + 3]);
        }
    }
}

// ---------------- x_proj GEMM (N=44, scalar guarded) ----------------
__global__ __launch_bounds__(256) void gemm_ng(
    const float* __restrict__ A, const float* __restrict__ W,
    float* __restrict__ C, int M, int N, int K)
{
    constexpr int BM = 64, BN = 64, BK = 8, TM = 4, TN = 4;
    __shared__ float As[2][BK][BM];
    __shared__ float Ws[BK][BN];   // single-buffer W (re-staged per tile), double-buffer A

    int tid = threadIdx.x;
    int bm  = blockIdx.y * BM;
    int tx  = tid & 15;
    int ty  = tid >> 4;

    float acc[TM][TN];
    #pragma unroll
    for (int i = 0; i < TM; i++)
        #pragma unroll
        for (int j = 0; j < TN; j++) acc[i][j] = 0.f;

    // A loader: 128 float4s
    bool doA = tid < 128;
    int am = tid >> 1, akp = (tid & 1) * 4;
    const float* Ap = A + (size_t)(bm + am) * K + akp;

    float4 pa = make_float4(0, 0, 0, 0);
    if (doA) {
        pa = *reinterpret_cast<const float4*>(Ap);
        As[0][akp + 0][am] = pa.x; As[0][akp + 1][am] = pa.y;
        As[0][akp + 2][am] = pa.z; As[0][akp + 3][am] = pa.w;
    }
    #pragma unroll
    for (int i = tid; i < BK * BN; i += 256) {
        int kk = i / BN, n = i % BN;
        Ws[kk][n] = (n < N) ? W[(size_t)kk * N + n] : 0.f;
    }
    __syncthreads();

    int nT = K / BK;
    for (int t = 0; t < nT; t++) {
        int cur = t & 1;
        float wsc[2]; int wn[2] = {-1, -1}, wk[2] = {0, 0};
        if (t + 1 < nT) {
            if (doA) pa = *reinterpret_cast<const float4*>(Ap + (size_t)(t + 1) * BK);
            // each thread covers 2 scalar W elems of next tile (8*44=352 <= 512)
            #pragma unroll
            for (int h = 0; h < 2; h++) {
                int i = tid + h * 256;
                if (i < BK * N) {
                    wk[h] = i / N; wn[h] = i % N;
                    wsc[h] = W[(size_t)((t + 1) * BK + wk[h]) * N + wn[h]];
                }
            }
        }
        #pragma unroll
        for (int kk = 0; kk < BK; kk++) {
            float ra[TM], rb[TN];
            #pragma unroll
            for (int i = 0; i < TM; i += 4)
                *reinterpret_cast<float4*>(&ra[i]) =
                    *reinterpret_cast<const float4*>(&As[cur][kk][ty * TM + i]);
            #pragma unroll
            for (int j = 0; j < TN; j += 4)
                *reinterpret_cast<float4*>(&rb[j]) =
                    *reinterpret_cast<const float4*>(&Ws[kk][tx * TN + j]);
            #pragma unroll
            for (int i = 0; i < TM; i++)
                #pragma unroll
                for (int j = 0; j < TN; j++)
                    acc[i][j] = fmaf(ra[i], rb[j], acc[i][j]);
        }
        if (t + 1 < nT) {
            __syncthreads();   // everyone done reading Ws before overwrite
            int nxt = cur ^ 1;
            if (doA) {
                As[nxt][akp + 0][am] = pa.x; As[nxt][akp + 1][am] = pa.y;
                As[nxt][akp + 2][am] = pa.z; As[nxt][akp + 3][am] = pa.w;
            }
            #pragma unroll
            for (int h = 0; h < 2; h++)
                if (wn[h] >= 0) Ws[wk[h]][wn[h]] = wsc[h];
            __syncthreads();
        }
    }

    #pragma unroll
    for (int i = 0; i < TM; i++) {
        int row = bm + ty * TM + i;
        #pragma unroll
        for (int j = 0; j < TN; j++) {
            int col = tx * TN + j;
            if (col < N) C[(size_t)row * N + col] = acc[i][j];
        }
    }
}

// ---------------- causal depthwise conv1d (k=4) + SiLU ----------------
__global__ void k_conv1d(const float* __restrict__ xz, const float* __restrict__ cw,
                         const float* __restrict__ cb, float* __restrict__ xc, int total)
{
    int i = blockIdx.x * blockDim.x + threadIdx.x;
    if (i >= total) return;
    int d = i % DINNER;
    int r = i / DINNER;
    int l = r & 1023;
    int b = r >> 10;
    float acc = cb[d];
    #pragma unroll
    for (int k = 0; k < 4; k++) {
        int ls = l + k - 3;
        if (ls >= 0)
            acc = fmaf(cw[d * 4 + k], xz[(size_t)((b << 10) + ls) * 768 + d], acc);
    }
    float sg = 1.f / (1.f + __expf(-acc));
    xc[i] = acc * sg;
}

// ---------------- dt = softplus(proj[:, :12] @ dt_proj_w + dt_proj_b) ----------------
__global__ __launch_bounds__(DINNER) void k_dt(
    const float* __restrict__ proj, const float* __restrict__ dtw,
    const float* __restrict__ dtb, float* __restrict__ dt)
{
    int row = blockIdx.x;
    int d   = threadIdx.x;
    float acc = dtb[d];
    #pragma unroll
    for (int r = 0; r < DTRANK; r++)
        acc = fmaf(proj[(size_t)row * NPROJ + r], dtw[r * DINNER + d], acc);
    float v = (acc > 20.f) ? acc : log1pf(__expf(acc));
    dt[(size_t)row * DINNER + d] = v;
}

// ---------------- selective scan + skip + gate, fused ----------------
__global__ __launch_bounds__(128) void k_scan(
    const float* __restrict__ dt, const float* __restrict__ xc,
    const float* __restrict__ proj, const float* __restrict__ A_log,
    const float* __restrict__ Dp, const float* __restrict__ xz,
    float* __restrict__ ys)
{
    constexpr int G = 8, CH = 32;
    __shared__ float s_dt[CH][G];
    __shared__ float s_xc[CH][G];
    __shared__ float s_z [CH][G];
    __shared__ float s_bc[CH][2 * DSTATE];

    int blk = blockIdx.x;
    int b   = blk / (DINNER / G);
    int d0  = (blk % (DINNER / G)) * G;
    int tid = threadIdx.x;
    int dg  = tid >> 4;
    int n   = tid & 15;
    int d   = d0 + dg;

    float A  = -expf(A_log[d * DSTATE + n]);
    float Dv = Dp[d];
    float h  = 0.f;

    for (int c0 = 0; c0 < LSEQ; c0 += CH) {
        int r0 = (b << 10) + c0;
        #pragma unroll
        for (int it = 0; it < 2; it++) {
            int i = tid + it * 128;
            int t = i >> 3, g2 = i & 7;
            s_dt[t][g2] = dt[(size_t)(r0 + t) * DINNER + d0 + g2];
            s_xc[t][g2] = xc[(size_t)(r0 + t) * DINNER + d0 + g2];
            s_z [t][g2] = xz[(size_t)(r0 + t) * 768 + DINNER + d0 + g2];
        }
        #pragma unroll
        for (int it = 0; it < 8; it++) {
            int i = tid + it * 128;
            int t = i >> 5, j = i & 31;
            s_bc[t][j] = proj[(size_t)(r0 + t) * NPROJ + DTRANK + j];
        }
        __syncthreads();

        #pragma unroll 4
        for (int t = 0; t < CH; t++) {
            float dtv = s_dt[t][dg];
            float xv  = s_xc[t][dg];
            float bv  = s_bc[t][n];
            float cv  = s_bc[t][DSTATE + n];
            float dA  = __expf(dtv * A);
            h = fmaf(dA, h, dtv * xv * bv);
            float p = h * cv;
            p += __shfl_xor_sync(0xffffffffu, p, 8);
            p += __shfl_xor_sync(0xffffffffu, p, 4);
            p += __shfl_xor_sync(0xffffffffu, p, 2);
            p += __shfl_xor_sync(0xffffffffu, p, 1);
            if (n == 0) {
                float z  = s_z[t][dg];
                float sg = 1.f / (1.f + __expf(-z));
                ys[(size_t)(r0 + t) * DINNER + d] = (p + xv * Dv) * (z * sg);
            }
        }
        __syncthreads();
    }
}

// ---------------- launch ----------------
extern "C" void kernel_launch(void* const* d_in, const int* in_sizes, int n_in,
                              void* d_out, int out_size)
{
    const float* x         = (const float*)d_in[0];
    const float* dwconv_w  = (const float*)d_in[1];
    const float* dwconv_b  = (const float*)d_in[2];
    const float* norm_w    = (const float*)d_in[3];
    const float* norm_b    = (const float*)d_in[4];
    const float* pw1_w     = (const float*)d_in[5];
    const float* pw1_b     = (const float*)d_in[6];
    const float* pw2_w     = (const float*)d_in[7];
    const float* pw2_b     = (const float*)d_in[8];
    const float* in_proj_w = (const float*)d_in[9];
    const float* conv1d_w  = (const float*)d_in[10];
    const float* conv1d_b  = (const float*)d_in[11];
    const float* x_proj_w  = (const float*)d_in[12];
    const float* dt_proj_w = (const float*)d_in[13];
    const float* dt_proj_b = (const float*)d_in[14];
    const float* A_log     = (const float*)d_in[15];
    const float* Dp        = (const float*)d_in[16];
    const float* out_proj_w= (const float*)d_in[17];

    float *ga, *gb, *gxc, *gproj, *gdt, *gys;
    cudaGetSymbolAddress((void**)&ga,    g_a);
    cudaGetSymbolAddress((void**)&gb,    g_b);
    cudaGetSymbolAddress((void**)&gxc,   g_xc);
    cudaGetSymbolAddress((void**)&gproj, g_proj);
    cudaGetSymbolAddress((void**)&gdt,   g_dt);
    cudaGetSymbolAddress((void**)&gys,   g_ys);

    // 1) depthwise conv -> gb (NHWC), LN in-place
    k_dw<<<BATCH * DIM, 256>>>(x, dwconv_w, dwconv_b, gb);
    k_ln<<<NROW / 8, 256>>>(gb, norm_w, norm_b);

    // 2) pw1 + GELU -> ga [8192 x 768]
    gemm3<128, 128, 8, 8, 1><<<dim3(6, 64), 256>>>(
        gb, pw1_w, pw1_b, ga, NROW, 768, DIM, nullptr);

    // 3) pw2 + bias -> gb [8192 x 192]  (64x64 tiles -> 384 CTAs)
    gemm3<64, 64, 4, 4, 0><<<dim3(3, 128), 256>>>(
        ga, pw2_w, pw2_b, gb, NROW, DIM, 768, nullptr);

    // 4) in_proj -> ga [8192 x 768]
    gemm3<128, 128, 8, 8, 2><<<dim3(6, 64), 256>>>(
        gb, in_proj_w, nullptr, ga, NROW, 768, DIM, nullptr);

    // 5) causal conv1d + SiLU -> gxc
    int tot = NROW * DINNER;
    k_conv1d<<<(tot + 255) / 256, 256>>>(ga, conv1d_w, conv1d_b, gxc, tot);

    // 6) x_proj -> gproj [8192 x 44]
    gemm_ng<<<dim3(1, 128), 256>>>(gxc, x_proj_w, gproj, NROW, NPROJ, DINNER);

    // 7) dt
    k_dt<<<NROW, DINNER>>>(gproj, dt_proj_w, dt_proj_b, gdt);

    // 8) selective scan + skip + gate -> gys
    k_scan<<<BATCH * (DINNER / 8), 128>>>(gdt, gxc, gproj, A_log, Dp, ga, gys);

    // 9) out_proj + transpose + residual -> d_out (64x64 tiles -> 384 CTAs)
    gemm3<64, 64, 4, 4, 3><<<dim3(3, 128), 256>>>(
        gys, out_proj_w, nullptr, (float*)d_out, NROW, DIM, DINNER, x);
}